// round 9
// baseline (speedup 1.0000x reference)
#include <cuda_runtime.h>

#define BATCH 4
#define NCTX  1024
#define NG    128

// Static device scratch (allocation-free per harness rules).
// Layout [b][n][axis-index] so per-n rows of 128 floats are contiguous (coalesced).
__device__ float g_U [BATCH][NCTX][NG];   // exp(-0.5*(gx[ix]-X0)^2)
__device__ float g_V0[BATCH][NCTX][NG];   // exp(-0.5*(gy[iy]-X1)^2)
__device__ float g_V1[BATCH][NCTX][NG];   // V * Y0
__device__ float g_V2[BATCH][NCTX][NG];   // V * Y1

// Kernel 1: one block per (b,n) context point, 128 threads = one thread per axis index.
__global__ void convcnp_encode_basis(const float* __restrict__ X,
                                     const float* __restrict__ Y,
                                     const float* __restrict__ grid) {
    int bn = blockIdx.x;          // b*1024 + n
    int b  = bn >> 10;
    int n  = bn & 1023;
    int t  = threadIdx.x;         // 0..127

    float x0 = X[bn * 2 + 0];
    float x1 = X[bn * 2 + 1];
    float y0 = Y[bn * 2 + 0];
    float y1 = Y[bn * 2 + 1];

    // grid[g] with g = ix*128 + iy; point = (gx[ix], gy[iy])
    float gx = grid[t * 256];      // grid[(t*128)*2 + 0]  -> gx[t]
    float gy = grid[t * 2 + 1];    // grid[t*2 + 1]        -> gy[t]

    float du = gx - x0;
    float dv = gy - x1;
    float u  = __expf(-0.5f * du * du);
    float v  = __expf(-0.5f * dv * dv);

    g_U [b][n][t] = u;
    g_V0[b][n][t] = v;
    g_V1[b][n][t] = v * y0;
    g_V2[b][n][t] = v * y1;
}

// Kernel 2: FM[b,ix,iy,c] = sum_n U[b,ix,n] * Vc[b,iy,n]; epilogue divides by density
// and writes the transposed output out[b,c,iy,ix].
#define TIX 32
#define TIY 16
#define KC  64

__global__ __launch_bounds__(256) void convcnp_contract(float* __restrict__ out) {
    __shared__ float Us [KC][TIX];
    __shared__ float V0s[KC][TIY];
    __shared__ float V1s[KC][TIY];
    __shared__ float V2s[KC][TIY];

    int b   = blockIdx.z;
    int ixb = blockIdx.x * TIX;
    int iyb = blockIdx.y * TIY;
    int tid = threadIdx.x;
    int iyl = tid & 15;       // 0..15 : iy within tile
    int ixl = tid >> 4;       // 0..15 : ix pair index (owns ix = ixb+2*ixl, +1)

    float a00 = 0.f, a01 = 0.f;   // density  (channel 0)  for ix0, ix1
    float a10 = 0.f, a11 = 0.f;   // channel 1
    float a20 = 0.f, a21 = 0.f;   // channel 2

    for (int n0 = 0; n0 < NCTX; n0 += KC) {
        // Stage K-chunk into shared (coalesced: rows of 32 / 16 floats).
        #pragma unroll
        for (int i = tid; i < KC * TIX; i += 256) {
            int k = i >> 5, ixo = i & 31;
            Us[k][ixo] = g_U[b][n0 + k][ixb + ixo];
        }
        #pragma unroll
        for (int i = tid; i < KC * TIY; i += 256) {
            int k = i >> 4, iyo = i & 15;
            V0s[k][iyo] = g_V0[b][n0 + k][iyb + iyo];
            V1s[k][iyo] = g_V1[b][n0 + k][iyb + iyo];
            V2s[k][iyo] = g_V2[b][n0 + k][iyb + iyo];
        }
        __syncthreads();

        #pragma unroll 8
        for (int k = 0; k < KC; k++) {
            float u0 = Us[k][2 * ixl];
            float u1 = Us[k][2 * ixl + 1];
            float v0 = V0s[k][iyl];
            float v1 = V1s[k][iyl];
            float v2 = V2s[k][iyl];
            a00 += u0 * v0;  a01 += u1 * v0;
            a10 += u0 * v1;  a11 += u1 * v1;
            a20 += u0 * v2;  a21 += u1 * v2;
        }
        __syncthreads();
    }

    // Epilogue: density division + transpose to out[b, c, iy, ix]
    int ix0 = ixb + 2 * ixl;
    int iy  = iyb + iyl;
    int base = (b * 3) << 14;          // 128*128 = 16384 = 1<<14
    int row  = (iy << 7);

    out[base + row + ix0    ] = a00;
    out[base + row + ix0 + 1] = a01;
    out[base + (1 << 14) + row + ix0    ] = a10 / a00;
    out[base + (1 << 14) + row + ix0 + 1] = a11 / a01;
    out[base + (2 << 14) + row + ix0    ] = a20 / a00;
    out[base + (2 << 14) + row + ix0 + 1] = a21 / a01;
}

extern "C" void kernel_launch(void* const* d_in, const int* in_sizes, int n_in,
                              void* d_out, int out_size) {
    const float* X    = (const float*)d_in[0];
    const float* Y    = (const float*)d_in[1];
    const float* grid = (const float*)d_in[2];
    float* out = (float*)d_out;

    convcnp_encode_basis<<<BATCH * NCTX, NG>>>(X, Y, grid);

    dim3 g(NG / TIX, NG / TIY, BATCH);   // 4 x 8 x 4 = 128 blocks
    convcnp_contract<<<g, 256>>>(out);
}

// round 12
// speedup vs baseline: 1.8901x; 1.8901x over previous
#include <cuda_runtime.h>

#define BATCH  4
#define NCTX   1024
#define NG     128
#define KSPLIT 8
#define NK     (NCTX / KSPLIT)   // 128 context points per split
#define KC     32                // k-chunk staged in shared
#define TI     32                // tile edge (both ix and iy)

// Static device scratch (allocation-free per harness rules).
__device__ float g_U [BATCH][NCTX][NG];   // exp(-0.5*(gx[ix]-X0)^2)
__device__ float g_V0[BATCH][NCTX][NG];   // exp(-0.5*(gy[iy]-X1)^2)
__device__ float g_V1[BATCH][NCTX][NG];   // V * Y0
__device__ float g_V2[BATCH][NCTX][NG];   // V * Y1
__device__ float g_part[KSPLIT][BATCH][3][NG][NG];   // split-K partial sums (6.3 MB)

// ── Kernel 1: per-(b,n) separable basis, 128 threads = one per axis index ──
__global__ void convcnp_encode_basis(const float* __restrict__ X,
                                     const float* __restrict__ Y,
                                     const float* __restrict__ grid) {
    int bn = blockIdx.x;
    int b  = bn >> 10;
    int n  = bn & 1023;
    int t  = threadIdx.x;

    float x0 = X[bn * 2 + 0];
    float x1 = X[bn * 2 + 1];
    float y0 = Y[bn * 2 + 0];
    float y1 = Y[bn * 2 + 1];

    // grid[g] with g = ix*128 + iy; point = (gx[ix], gy[iy])
    float gx = grid[t * 256];      // gx[t]
    float gy = grid[t * 2 + 1];    // gy[t]

    float du = gx - x0;
    float dv = gy - x1;
    float u  = __expf(-0.5f * du * du);
    float v  = __expf(-0.5f * dv * dv);

    g_U [b][n][t] = u;
    g_V0[b][n][t] = v;
    g_V1[b][n][t] = v * y0;
    g_V2[b][n][t] = v * y1;
}

// ── Kernel 2: split-K rank-NK outer products, 2x2x3 register blocking ──
// blockIdx.z = b*KSPLIT + ks.  Tile: 32 ix × 32 iy; thread owns 2 ix × 2 iy × 3 ch.
__global__ __launch_bounds__(256) void convcnp_contract() {
    __shared__ float Us [KC][TI];
    __shared__ float V0s[KC][TI];
    __shared__ float V1s[KC][TI];
    __shared__ float V2s[KC][TI];

    int bz  = blockIdx.z;
    int b   = bz >> 3;            // / KSPLIT
    int ks  = bz & 7;             // % KSPLIT
    int ixb = blockIdx.x * TI;
    int iyb = blockIdx.y * TI;
    int tid = threadIdx.x;
    int ixl = tid & 15;           // ix pair index
    int iyl = tid >> 4;           // iy pair index

    float acc[3][2][2] = {};      // [channel][iy_j][ix_i]
    int nbase = ks * NK;

    for (int n0 = 0; n0 < NK; n0 += KC) {
        #pragma unroll
        for (int i = tid; i < KC * TI; i += 256) {
            int k = i >> 5, o = i & 31;
            int n = nbase + n0 + k;
            Us [k][o] = g_U [b][n][ixb + o];
            V0s[k][o] = g_V0[b][n][iyb + o];
            V1s[k][o] = g_V1[b][n][iyb + o];
            V2s[k][o] = g_V2[b][n][iyb + o];
        }
        __syncthreads();

        #pragma unroll 4
        for (int k = 0; k < KC; k++) {
            float2 u  = *(const float2*)&Us [k][2 * ixl];
            float2 v0 = *(const float2*)&V0s[k][2 * iyl];
            float2 v1 = *(const float2*)&V1s[k][2 * iyl];
            float2 v2 = *(const float2*)&V2s[k][2 * iyl];
            acc[0][0][0] += u.x * v0.x;  acc[0][0][1] += u.y * v0.x;
            acc[0][1][0] += u.x * v0.y;  acc[0][1][1] += u.y * v0.y;
            acc[1][0][0] += u.x * v1.x;  acc[1][0][1] += u.y * v1.x;
            acc[1][1][0] += u.x * v1.y;  acc[1][1][1] += u.y * v1.y;
            acc[2][0][0] += u.x * v2.x;  acc[2][0][1] += u.y * v2.x;
            acc[2][1][0] += u.x * v2.y;  acc[2][1][1] += u.y * v2.y;
        }
        __syncthreads();
    }

    int ix0 = ixb + 2 * ixl;
    #pragma unroll
    for (int c = 0; c < 3; c++) {
        #pragma unroll
        for (int j = 0; j < 2; j++) {
            int iy = iyb + 2 * iyl + j;
            float2 w = make_float2(acc[c][j][0], acc[c][j][1]);
            *(float2*)&g_part[ks][b][c][iy][ix0] = w;
        }
    }
}

// ── Kernel 3: reduce KSPLIT partials, density division, write out[b,c,iy,ix] ──
__global__ __launch_bounds__(256) void convcnp_finalize(float* __restrict__ out) {
    int idx = blockIdx.x * 256 + threadIdx.x;   // b*16384 + pos
    int b   = idx >> 14;
    int pos = idx & 16383;                      // iy*128 + ix

    const float* base = (const float*)g_part;
    float s0 = 0.f, s1 = 0.f, s2 = 0.f;
    #pragma unroll
    for (int ks = 0; ks < KSPLIT; ks++) {
        int p = ((ks * BATCH + b) * 3) << 14;
        s0 += base[p + pos];
        s1 += base[p + (1 << 14) + pos];
        s2 += base[p + (2 << 14) + pos];
    }
    int o = (b * 3) << 14;
    out[o + pos]             = s0;
    out[o + (1 << 14) + pos] = s1 / s0;
    out[o + (2 << 14) + pos] = s2 / s0;
}

extern "C" void kernel_launch(void* const* d_in, const int* in_sizes, int n_in,
                              void* d_out, int out_size) {
    const float* X    = (const float*)d_in[0];
    const float* Y    = (const float*)d_in[1];
    const float* grid = (const float*)d_in[2];
    float* out = (float*)d_out;

    convcnp_encode_basis<<<BATCH * NCTX, NG>>>(X, Y, grid);

    dim3 g(NG / TI, NG / TI, BATCH * KSPLIT);   // 4 x 4 x 32 = 512 CTAs
    convcnp_contract<<<g, 256>>>();

    convcnp_finalize<<<(BATCH * NG * NG) / 256, 256>>>(out);
}